// round 16
// baseline (speedup 1.0000x reference)
#include <cuda_runtime.h>
#include <cuda_bf16.h>
#include <cstdint>
#include <math.h>

// ---------------------------------------------------------------------------
// Performer (FAVOR+) encoder. tf32 mma.sync GEMMs, 3-stage cp.async pipeline,
// col-fastest rasterization, B operand cached in L1 (.ca); embed with 8-token
// weight reuse; producer-side tf32 rounding; fused FAVOR+ features; exp+ksum
// folded into context GEMM. B=8 S=8192 H=256 HEADS=8 DH=32 M=64 L=4 FF=1024
// ---------------------------------------------------------------------------

namespace {
constexpr int Bc = 8, Sc = 8192, INc = 64, Hc = 256;
constexpr int HEADSc = 8, DHc = 32, Mc = 64, Lc = 4;
constexpr int FFc = 1024;
constexpr int NTOK = Bc * Sc;          // 65536
constexpr int BHc = Bc * HEADSc;       // 64
constexpr int QKVc = 3 * Hc;           // 768
constexpr int GEMM_SMEM = 3 * (16384 + 16384);   // 96KB
constexpr int CTX_SPLITS = 32;
}

// scratch (all fp32)
__device__ float g_h[(size_t)NTOK * Hc];
__device__ float g_ln[(size_t)NTOK * Hc];
__device__ float g_qkv[(size_t)NTOK * QKVc];
__device__ float g_attn[(size_t)NTOK * Hc];
__device__ float g_ff[(size_t)NTOK * FFc];
__device__ float g_qp[(size_t)NTOK * HEADSc * Mc];   // [bh][s][m] features
__device__ float g_kp[(size_t)NTOK * HEADSc * Mc];   // [bh][s][m] RAW xp-diag
__device__ float g_ctx[BHc * Mc * DHc];
__device__ float g_ksum[BHc * Mc];
__device__ float g_bhmax[BHc];
__device__ float g_pooled[Bc * Hc];
// pre-transposed (and tf32-rounded) weights
__device__ __align__(16) float g_wqkv_t[(size_t)Lc * QKVc * Hc];
__device__ __align__(16) float g_wo_t[(size_t)Lc * Hc * Hc];
__device__ __align__(16) float g_w1_t[(size_t)Lc * FFc * Hc];
__device__ __align__(16) float g_w2_t[(size_t)Lc * Hc * FFc];

__device__ __forceinline__ void atomicMaxF(float* addr, float val) {
    if (val >= 0.0f) atomicMax((int*)addr, __float_as_int(val));
    else             atomicMin((unsigned int*)addr, __float_as_uint(val));
}

// ------------------------- helpers ----------------------------------------
__device__ __forceinline__ uint32_t smem_u32(const void* p) {
    uint32_t a;
    asm("{ .reg .u64 t; cvta.to.shared.u64 t, %1; cvt.u32.u64 %0, t; }"
        : "=r"(a) : "l"(p));
    return a;
}
__device__ __forceinline__ float rtf32(float f) {
    uint32_t r;
    asm("cvt.rna.tf32.f32 %0, %1;" : "=r"(r) : "f"(f));
    return __uint_as_float(r);
}
__device__ __forceinline__ void mma1688_tf32(float* d, const uint32_t* a,
                                             const uint32_t* b) {
    asm volatile(
        "mma.sync.aligned.m16n8k8.row.col.f32.tf32.tf32.f32 "
        "{%0,%1,%2,%3},{%4,%5,%6,%7},{%8,%9},{%0,%1,%2,%3};"
        : "+f"(d[0]), "+f"(d[1]), "+f"(d[2]), "+f"(d[3])
        : "r"(a[0]), "r"(a[1]), "r"(a[2]), "r"(a[3]), "r"(b[0]), "r"(b[1]));
}
__device__ __forceinline__ void cpasync16(uint32_t saddr, const void* g) {
    asm volatile("cp.async.cg.shared.global [%0], [%1], 16;" :: "r"(saddr), "l"(g));
}
__device__ __forceinline__ void cpasync16_ca(uint32_t saddr, const void* g) {
    asm volatile("cp.async.ca.shared.global [%0], [%1], 16;" :: "r"(saddr), "l"(g));
}
__device__ __forceinline__ void cp_commit() {
    asm volatile("cp.async.commit_group;" ::: "memory");
}
template <int N>
__device__ __forceinline__ void cp_wait() {
    asm volatile("cp.async.wait_group %0;" :: "n"(N) : "memory");
}

// ---------------------------------------------------------------------------
// tf32 MMA GEMM: C[NTOK,Ntot] = A[NTOK,K] @ Bt[Ntot,K]^T
// CTA tile 128x128, BK=32, 3-stage cp.async pipeline, ONE sync per k-chunk.
// grid = (Ntot/128, M/128) col-fastest. A streams (.cg), B cached in L1 (.ca).
// EPI: 0=none, 2=bias+res, 3=bias+gelu(exact, rna out)
// ---------------------------------------------------------------------------
template <int EPI>
__global__ void __launch_bounds__(256, 2)
k_mma(const float* __restrict__ A, const float* __restrict__ Bt,
      const float* __restrict__ bias, const float* __restrict__ res,
      float* __restrict__ C, int K, int Ntot) {
    extern __shared__ char smem[];
    const uint32_t sbase = smem_u32(smem);
    const int t = threadIdx.x;
    const int w = t >> 5, lane = t & 31;
    const int row0 = blockIdx.y * 128, col0 = blockIdx.x * 128;
    const int wm = (w & 3) * 32, wn = (w >> 2) * 64;
    const int gid = lane >> 2, tig = lane & 3;

    float acc[2][8][4];
#pragma unroll
    for (int mi = 0; mi < 2; mi++)
#pragma unroll
        for (int ni = 0; ni < 8; ni++)
#pragma unroll
            for (int j = 0; j < 4; j++) acc[mi][ni][j] = 0.f;

    const int nsteps = K >> 5;

    auto load_step = [&](int kc, int buf) {
        const float* Ag = A + (size_t)row0 * K + kc * 32;
        const float* Bg = Bt + (size_t)col0 * K + kc * 32;
        uint32_t sA = sbase + buf * 32768u;
        uint32_t sB = sA + 16384u;
#pragma unroll
        for (int i = 0; i < 4; i++) {
            int id = t + i * 256;
            int r = id >> 3, c = id & 7;
            uint32_t so = (uint32_t)(r * 128 + ((c ^ (r & 7)) << 4));
            cpasync16(sA + so, Ag + (size_t)r * K + c * 4);
            cpasync16_ca(sB + so, Bg + (size_t)r * K + c * 4);
        }
        cp_commit();
    };

    load_step(0, 0);
    if (nsteps > 1) load_step(1, 1);

    for (int kc = 0; kc < nsteps; kc++) {
        if (kc + 1 < nsteps) cp_wait<1>();
        else                 cp_wait<0>();
        __syncthreads();
        if (kc + 2 < nsteps) load_step(kc + 2, (kc + 2) % 3);

        const char* smA = smem + (kc % 3) * 32768;
        const char* smB = smA + 16384;
#pragma unroll
        for (int k8 = 0; k8 < 4; k8++) {
            uint32_t a[2][4];
#pragma unroll
            for (int mi = 0; mi < 2; mi++) {
#pragma unroll
                for (int j = 0; j < 4; j++) {
                    int row = wm + mi * 16 + gid + ((j & 1) ? 8 : 0);
                    int wc = k8 * 8 + tig + ((j & 2) ? 4 : 0);
                    a[mi][j] = *(const uint32_t*)(smA + row * 128 +
                                                  (((wc >> 2) ^ (row & 7)) << 4) +
                                                  (wc & 3) * 4);
                }
            }
            uint32_t b[8][2];
#pragma unroll
            for (int ni = 0; ni < 8; ni++) {
#pragma unroll
                for (int j = 0; j < 2; j++) {
                    int wc = k8 * 8 + tig + j * 4;
                    int n = wn + ni * 8 + gid;
                    b[ni][j] = *(const uint32_t*)(smB + n * 128 +
                                                  (((wc >> 2) ^ (n & 7)) << 4) +
                                                  (wc & 3) * 4);
                }
            }
#pragma unroll
            for (int mi = 0; mi < 2; mi++)
#pragma unroll
                for (int ni = 0; ni < 8; ni++) mma1688_tf32(acc[mi][ni], a[mi], b[ni]);
        }
    }

#pragma unroll
    for (int mi = 0; mi < 2; mi++) {
#pragma unroll
        for (int ni = 0; ni < 8; ni++) {
            const int rg = row0 + wm + mi * 16 + gid;
            const int cg = col0 + wn + ni * 8 + tig * 2;
            const float* ac = acc[mi][ni];
#pragma unroll
            for (int half = 0; half < 2; half++) {
                const int row = rg + half * 8;
                float v0 = ac[half * 2], v1 = ac[half * 2 + 1];
                if (EPI >= 2) { v0 += bias[cg]; v1 += bias[cg + 1]; }
                if (EPI == 3) {
                    v0 = 0.5f * v0 * (1.0f + erff(v0 * 0.70710678118654752f));
                    v1 = 0.5f * v1 * (1.0f + erff(v1 * 0.70710678118654752f));
                    v0 = rtf32(v0);
                    v1 = rtf32(v1);
                }
                const size_t base = (size_t)row * Ntot + cg;
                if (EPI == 2) { v0 += res[base]; v1 += res[base + 1]; }
                C[base] = v0;
                C[base + 1] = v1;
            }
        }
    }
}

// ---------------------------------------------------------------------------
// weight transposes (rna-rounded)
// ---------------------------------------------------------------------------
__global__ void k_wt(const float* __restrict__ W, float* __restrict__ Wt,
                     int K, int N) {
    __shared__ float tile[32][33];
    int l = blockIdx.z;
    W += (size_t)l * K * N;
    Wt += (size_t)l * K * N;
    int kb = blockIdx.x * 32, nb = blockIdx.y * 32;
    int tx = threadIdx.x, ty = threadIdx.y;
#pragma unroll
    for (int i = ty; i < 32; i += 8) tile[i][tx] = W[(size_t)(kb + i) * N + nb + tx];
    __syncthreads();
#pragma unroll
    for (int i = ty; i < 32; i += 8)
        Wt[(size_t)(nb + i) * K + kb + tx] = rtf32(tile[tx][i]);
}

__global__ void k_wt_qkv(const float* __restrict__ wq, const float* __restrict__ wk,
                         const float* __restrict__ wv, float* __restrict__ Wt) {
    __shared__ float tile[32][33];
    int l = blockIdx.z;
    int kb = blockIdx.x * 32, nb = blockIdx.y * 32;
    const float* W = (nb < 256) ? wq : (nb < 512 ? wk : wv);
    int nloc = nb & 255;
    W += (size_t)l * Hc * Hc;
    Wt += (size_t)l * QKVc * Hc;
    int tx = threadIdx.x, ty = threadIdx.y;
#pragma unroll
    for (int i = ty; i < 32; i += 8)
        tile[i][tx] = W[(size_t)(kb + i) * Hc + nloc + tx];
    __syncthreads();
#pragma unroll
    for (int i = ty; i < 32; i += 8)
        Wt[(size_t)(nb + i) * Hc + kb + tx] = rtf32(tile[tx][i]);
}

// ---------------------------------------------------------------------------
// embed: 8 tokens/block; thread = out column; w loaded once per block and
// reused across 8 tokens in registers. grid NTOK/8, block 256.
// ---------------------------------------------------------------------------
__global__ void k_embed(const float* __restrict__ x, const float* __restrict__ w,
                        const float* __restrict__ b, const float* __restrict__ pos) {
    __shared__ float xs[8][INc];
    int t = threadIdx.x;
    size_t n0 = (size_t)blockIdx.x * 8;
    for (int i = t; i < 8 * INc; i += 256)
        xs[i >> 6][i & 63] = x[n0 * INc + i];
    __syncthreads();
    int s0 = (int)(n0 & (Sc - 1));
    float bias = b[t];
    float acc[8];
#pragma unroll
    for (int j = 0; j < 8; j++) acc[j] = bias + pos[(size_t)(s0 + j) * Hc + t];
#pragma unroll 8
    for (int d = 0; d < INc; d++) {
        float wv = w[(size_t)d * Hc + t];
#pragma unroll
        for (int j = 0; j < 8; j++) acc[j] += xs[j][d] * wv;
    }
#pragma unroll
    for (int j = 0; j < 8; j++) g_h[(n0 + j) * Hc + t] = acc[j];
}

// ---------------------------------------------------------------------------
// layernorm, warp per token, float4, rna out
// ---------------------------------------------------------------------------
__global__ void k_ln(const float* __restrict__ gamma, const float* __restrict__ beta) {
    int w = threadIdx.x >> 5, lane = threadIdx.x & 31;
    size_t n = (size_t)blockIdx.x * 8 + w;
    const float4* row = (const float4*)(g_h + n * Hc);
    float4 a = row[lane * 2], c = row[lane * 2 + 1];
    float s = a.x + a.y + a.z + a.w + c.x + c.y + c.z + c.w;
#pragma unroll
    for (int o = 16; o; o >>= 1) s += __shfl_xor_sync(~0u, s, o);
    float mu = s * (1.0f / Hc);
    float dx[8] = {a.x - mu, a.y - mu, a.z - mu, a.w - mu,
                   c.x - mu, c.y - mu, c.z - mu, c.w - mu};
    float v = 0.f;
#pragma unroll
    for (int i = 0; i < 8; i++) v += dx[i] * dx[i];
#pragma unroll
    for (int o = 16; o; o >>= 1) v += __shfl_xor_sync(~0u, v, o);
    float rstd = rsqrtf(v * (1.0f / Hc) + 1e-5f);
    float4 g0 = *(const float4*)(gamma + lane * 8);
    float4 g1 = *(const float4*)(gamma + lane * 8 + 4);
    float4 b0 = *(const float4*)(beta + lane * 8);
    float4 b1 = *(const float4*)(beta + lane * 8 + 4);
    float4 o0, o1;
    o0.x = rtf32(dx[0] * rstd * g0.x + b0.x);
    o0.y = rtf32(dx[1] * rstd * g0.y + b0.y);
    o0.z = rtf32(dx[2] * rstd * g0.z + b0.z);
    o0.w = rtf32(dx[3] * rstd * g0.w + b0.w);
    o1.x = rtf32(dx[4] * rstd * g1.x + b1.x);
    o1.y = rtf32(dx[5] * rstd * g1.y + b1.y);
    o1.z = rtf32(dx[6] * rstd * g1.z + b1.z);
    o1.w = rtf32(dx[7] * rstd * g1.w + b1.w);
    float4* orow = (float4*)(g_ln + n * Hc);
    orow[lane * 2] = o0;
    orow[lane * 2 + 1] = o1;
}

// ---------------------------------------------------------------------------
__global__ void k_init() {
    int i = blockIdx.x * blockDim.x + threadIdx.x;
    if (i < BHc * Mc * DHc) g_ctx[i] = 0.f;
    if (i < BHc * Mc) g_ksum[i] = 0.f;
    if (i < BHc) g_bhmax[i] = -INFINITY;
    if (i < Bc * Hc) g_pooled[i] = 0.f;
}

// ---------------------------------------------------------------------------
// FAVOR+ q and k feature maps in ONE launch. block=256 (8 warps),
// grid = NTOK/8. warp w handles head w for 8 consecutive tokens.
// ---------------------------------------------------------------------------
__global__ void k_favor_qk(const float* __restrict__ proj) {
    __shared__ float ps[Mc * 33];
    int t = threadIdx.x;
    for (int i = t; i < Mc * DHc; i += 256) ps[(i >> 5) * 33 + (i & 31)] = proj[i];
    __syncthreads();
    int w = t >> 5, lane = t & 31;
    int n0 = blockIdx.x * 8;
    int b = n0 / Sc;
    int bh = b * HEADSc + w;
    const float NORM = 0.4204482076268573f;  // 32^-0.25

    // ---------------- q features ----------------
#pragma unroll
    for (int it = 0; it < 2; it++) {
        float qv[4], diag[4];
#pragma unroll
        for (int j = 0; j < 4; j++) {
            qv[j] = g_qkv[(size_t)(n0 + it * 4 + j) * QKVc + w * DHc + lane] * NORM;
            float sq = qv[j] * qv[j];
#pragma unroll
            for (int o = 16; o; o >>= 1) sq += __shfl_xor_sync(~0u, sq, o);
            diag[j] = 0.5f * sq;
        }
        float xp0[4] = {0.f, 0.f, 0.f, 0.f}, xp1[4] = {0.f, 0.f, 0.f, 0.f};
#pragma unroll
        for (int d = 0; d < DHc; d++) {
            float p0 = ps[lane * 33 + d];
            float p1 = ps[(lane + 32) * 33 + d];
#pragma unroll
            for (int j = 0; j < 4; j++) {
                float qd = __shfl_sync(~0u, qv[j], d);
                xp0[j] += qd * p0;
                xp1[j] += qd * p1;
            }
        }
#pragma unroll
        for (int j = 0; j < 4; j++) {
            float mx = fmaxf(xp0[j], xp1[j]);
#pragma unroll
            for (int o = 16; o; o >>= 1) mx = fmaxf(mx, __shfl_xor_sync(~0u, mx, o));
            int n = n0 + it * 4 + j;
            size_t idx = ((size_t)bh * Sc + (n & (Sc - 1))) * Mc + lane;
            g_qp[idx]      = 0.125f * (__expf(xp0[j] - diag[j] - mx) + 1e-4f);
            g_qp[idx + 32] = 0.125f * (__expf(xp1[j] - diag[j] - mx) + 1e-4f);
        }
    }

    // ---------------- k raw features + per-bh max ----------------
    float wmax = -INFINITY;
#pragma unroll
    for (int it = 0; it < 2; it++) {
        float kv[4], diag[4];
#pragma unroll
        for (int j = 0; j < 4; j++) {
            kv[j] = g_qkv[(size_t)(n0 + it * 4 + j) * QKVc + Hc + w * DHc + lane] * NORM;
            float sq = kv[j] * kv[j];
#pragma unroll
            for (int o = 16; o; o >>= 1) sq += __shfl_xor_sync(~0u, sq, o);
            diag[j] = 0.5f * sq;
        }
        float xp0[4] = {0.f, 0.f, 0.f, 0.f}, xp1[4] = {0.f, 0.f, 0.f, 0.f};
#pragma unroll
        for (int d = 0; d < DHc; d++) {
            float p0 = ps[lane * 33 + d];
            float p1 = ps[(lane + 32) * 33 + d];
#pragma unroll
            for (int j = 0; j < 4; j++) {
                float kd = __shfl_sync(~0u, kv[j], d);
                xp0[j] += kd * p0;
                xp1[j] += kd * p1;
            }
        }
#pragma unroll
        for (int j = 0; j < 4; j++) {
            wmax = fmaxf(wmax, fmaxf(xp0[j], xp1[j]));
            int n = n0 + it * 4 + j;
            size_t idx = ((size_t)bh * Sc + (n & (Sc - 1))) * Mc + lane;
            g_kp[idx]      = xp0[j] - diag[j];
            g_kp[idx + 32] = xp1[j] - diag[j];
        }
    }
#pragma unroll
    for (int o = 16; o; o >>= 1) wmax = fmaxf(wmax, __shfl_xor_sync(~0u, wmax, o));
    if (lane == 0) atomicMaxF(&g_bhmax[bh], wmax);
}

// ---------------------------------------------------------------------------
// context[m,e] = sum_n kp'[n,m] * v[n,e], kp' = 0.125*(exp(raw-mx)+1e-4)
// applied on tile load; ksum accumulated as by-product. split-K over n.
// grid (BHc, CTX_SPLITS), block 256.
// ---------------------------------------------------------------------------
__global__ void k_context() {
    int bh = blockIdx.x, split = blockIdx.y;
    int b = bh >> 3, h = bh & 7;
    const float mx = g_bhmax[bh];
    int t = threadIdx.x;
    int m = t & 63, eb = (t >> 6) * 8;
    __shared__ float kps[16][64];
    __shared__ __align__(16) float vs[16][32];
    float acc[8];
#pragma unroll
    for (int j = 0; j < 8; j++) acc[j] = 0.f;
    float ksl = 0.f;
    int nbase = split * (Sc / CTX_SPLITS);
    for (int tile = 0; tile < (Sc / CTX_SPLITS) / 16; tile++) {
        int n0 = nbase + tile * 16;
        for (int i = t; i < 16 * 64; i += 256) {
            int r = i >> 6, mm = i & 63;
            float raw = g_kp[((size_t)bh * Sc + n0 + r) * Mc + mm];
            kps[r][mm] = 0.125f * (__expf(raw - mx) + 1e-4f);
        }
        for (int i = t; i < 16 * 32; i += 256) {
            int r = i >> 5, e = i & 31;
            vs[r][e] = g_qkv[((size_t)(b * Sc + n0 + r)) * QKVc + 2 * Hc + h * DHc + e];
        }
        __syncthreads();
#pragma unroll
        for (int r = 0; r < 16; r++) {
            float kvv = kps[r][m];
            ksl += kvv;
            float4 va = *(const float4*)&vs[r][eb];
            float4 vb = *(const float4*)&vs[r][eb + 4];
            acc[0] += kvv * va.x; acc[1] += kvv * va.y;
            acc[2] += kvv * va.z; acc[3] += kvv * va.w;
            acc[4] += kvv * vb.x; acc[5] += kvv * vb.y;
            acc[6] += kvv * vb.z; acc[7] += kvv * vb.w;
        }
        __syncthreads();
    }
#pragma unroll
    for (int j = 0; j < 8; j++)
        atomicAdd(&g_ctx[(bh * Mc + m) * DHc + eb + j], acc[j]);
    if (t < 64) atomicAdd(&g_ksum[bh * Mc + m], ksl);
}

// ---------------------------------------------------------------------------
// attn out: out[n, h*32+e] = (qp[n,:] @ ctx) / (qp[n,:] . ksum), rna out
// ---------------------------------------------------------------------------
__global__ void __launch_bounds__(256) k_attn_out() {
    int bh = blockIdx.x;
    int b = bh >> 3, h = bh & 7;
    int n0 = blockIdx.y * 128;
    int t = threadIdx.x;
    __shared__ float qps[128 * 68];
    __shared__ __align__(16) float ctxs[64 * 36];
    __shared__ float ks[64];
    const float4* qpg = (const float4*)(g_qp + ((size_t)bh * Sc + n0) * Mc);
    for (int i = t; i < 2048; i += 256) {
        int r = i >> 4, c = i & 15;
        float4 v = qpg[r * 16 + c];
        float* dst = &qps[r * 68 + c * 4];
        dst[0] = v.x; dst[1] = v.y; dst[2] = v.z; dst[3] = v.w;
    }
    for (int i = t; i < 64 * 32; i += 256) {
        int m = i >> 5, e = i & 31;
        ctxs[m * 36 + e] = g_ctx[(bh * Mc + m) * DHc + e];
    }
    if (t < 64) ks[t] = g_ksum[bh * Mc + t];
    __syncthreads();

    int tok = t >> 1, eg = (t & 1) * 16;
    float acc[16];
#pragma unroll
    for (int i = 0; i < 16; i++) acc[i] = 0.f;
    float dp = 0.f;
#pragma unroll 8
    for (int m = 0; m < 64; m++) {
        float qv = qps[tok * 68 + m];
        dp += qv * ks[m];
        const float4* c4 = (const float4*)&ctxs[m * 36 + eg];
        float4 c0 = c4[0], c1 = c4[1], c2 = c4[2], c3 = c4[3];
        acc[0] += qv * c0.x; acc[1] += qv * c0.y; acc[2] += qv * c0.z; acc[3] += qv * c0.w;
        acc[4] += qv * c1.x; acc[5] += qv * c1.y; acc[6] += qv * c1.z; acc[7] += qv * c1.w;
        acc[8] += qv * c2.x; acc[9] += qv * c2.y; acc[10] += qv * c2.z; acc[11] += qv * c2.w;
        acc[12] += qv * c3.x; acc[13] += qv * c3.y; acc[14] += qv * c3.z; acc[15] += qv * c3.w;
    }
    float inv = 1.0f / dp;
    float* outp = g_attn + ((size_t)(b * Sc + n0 + tok)) * Hc + h * DHc + eg;
#pragma unroll
    for (int q = 0; q < 4; q++) {
        float4 o;
        o.x = rtf32(acc[q * 4 + 0] * inv);
        o.y = rtf32(acc[q * 4 + 1] * inv);
        o.z = rtf32(acc[q * 4 + 2] * inv);
        o.w = rtf32(acc[q * 4 + 3] * inv);
        *(float4*)(outp + q * 4) = o;
    }
}

__global__ void k_pool() {
    int b = blockIdx.x, chunk = blockIdx.y, t = threadIdx.x;
    float s = 0.f;
    int r0 = chunk * 128;
#pragma unroll 4
    for (int r = 0; r < 128; r++) s += g_h[(size_t)(b * Sc + r0 + r) * Hc + t];
    atomicAdd(&g_pooled[b * Hc + t], s);
}

__global__ void k_fc(const float* __restrict__ fc_w, const float* __restrict__ fc_b,
                     float* __restrict__ out) {
    int t = threadIdx.x, w = t >> 5, lane = t & 31;
    if (w >= 16) return;
    int b = w >> 1, c = w & 1;
    float s = 0.f;
#pragma unroll
    for (int k = lane; k < Hc; k += 32) s += g_pooled[b * Hc + k] * fc_w[k * 2 + c];
#pragma unroll
    for (int o = 16; o; o >>= 1) s += __shfl_xor_sync(~0u, s, o);
    if (lane == 0) out[b * 2 + c] = s * (1.0f / Sc) + fc_b[c];
}

// ---------------------------------------------------------------------------
// launch  (k_mma<0> kept at launch index 3 for profiling)
// ---------------------------------------------------------------------------
extern "C" void kernel_launch(void* const* d_in, const int* /*in_sizes*/, int /*n_in*/,
                              void* d_out, int /*out_size*/) {
    const float* x     = (const float*)d_in[0];
    const float* emb_w = (const float*)d_in[1];
    const float* emb_b = (const float*)d_in[2];
    const float* pos   = (const float*)d_in[3];
    const float* ln1_g = (const float*)d_in[4];
    const float* ln1_b = (const float*)d_in[5];
    const float* wq    = (const float*)d_in[6];
    const float* wk    = (const float*)d_in[7];
    const float* wv    = (const float*)d_in[8];
    const float* wo    = (const float*)d_in[9];
    const float* bo    = (const float*)d_in[10];
    const float* ln2_g = (const float*)d_in[11];
    const float* ln2_b = (const float*)d_in[12];
    const float* w1    = (const float*)d_in[13];
    const float* b1    = (const float*)d_in[14];
    const float* w2    = (const float*)d_in[15];
    const float* b2    = (const float*)d_in[16];
    const float* proj  = (const float*)d_in[17];
    const float* fc_w  = (const float*)d_in[18];
    const float* fc_b  = (const float*)d_in[19];
    float* out = (float*)d_out;

    static float *p_h = nullptr, *p_ln = nullptr, *p_qkv = nullptr, *p_attn = nullptr,
                 *p_ff = nullptr, *p_wqkv = nullptr, *p_wo = nullptr,
                 *p_w1 = nullptr, *p_w2 = nullptr;
    if (!p_h) {
        cudaGetSymbolAddress((void**)&p_h, g_h);
        cudaGetSymbolAddress((void**)&p_ln, g_ln);
        cudaGetSymbolAddress((void**)&p_qkv, g_qkv);
        cudaGetSymbolAddress((void**)&p_attn, g_attn);
        cudaGetSymbolAddress((void**)&p_ff, g_ff);
        cudaGetSymbolAddress((void**)&p_wqkv, g_wqkv_t);
        cudaGetSymbolAddress((void**)&p_wo, g_wo_t);
        cudaGetSymbolAddress((void**)&p_w1, g_w1_t);
        cudaGetSymbolAddress((void**)&p_w2, g_w2_t);
        cudaFuncSetAttribute(k_mma<0>, cudaFuncAttributeMaxDynamicSharedMemorySize,
                             GEMM_SMEM);
        cudaFuncSetAttribute(k_mma<2>, cudaFuncAttributeMaxDynamicSharedMemorySize,
                             GEMM_SMEM);
        cudaFuncSetAttribute(k_mma<3>, cudaFuncAttributeMaxDynamicSharedMemorySize,
                             GEMM_SMEM);
    }

    dim3 wtb(32, 8);
    dim3 gQKV(QKVc / 128, NTOK / 128);   // (6, 512) col-fastest
    dim3 gH(Hc / 128, NTOK / 128);       // (2, 512)
    dim3 gFF(FFc / 128, NTOK / 128);     // (8, 512)

    // launch 0..3: embed, ln1(l0), wt_qkv, mma_qkv(l0)  -> k_mma<0> @ index 3
    k_embed<<<NTOK / 8, 256>>>(x, emb_w, emb_b, pos);
    k_ln<<<NTOK / 8, 256>>>(ln1_g, ln1_b);
    k_wt_qkv<<<dim3(Hc / 32, QKVc / 32, Lc), wtb>>>(wq, wk, wv, p_wqkv);
    k_mma<0><<<gQKV, 256, GEMM_SMEM>>>(p_ln, p_wqkv, nullptr, nullptr, p_qkv,
                                       Hc, QKVc);
    k_wt<<<dim3(Hc / 32, Hc / 32, Lc), wtb>>>(wo, p_wo, Hc, Hc);
    k_wt<<<dim3(Hc / 32, FFc / 32, Lc), wtb>>>(w1, p_w1, Hc, FFc);
    k_wt<<<dim3(FFc / 32, Hc / 32, Lc), wtb>>>(w2, p_w2, FFc, Hc);

    for (int l = 0; l < Lc; l++) {
        const float* bo_l = bo + (size_t)l * Hc;
        const float* b1_l = b1 + (size_t)l * FFc;
        const float* b2_l = b2 + (size_t)l * Hc;
        const float* pr_l = proj + (size_t)l * Mc * DHc;

        if (l > 0) {
            k_ln<<<NTOK / 8, 256>>>(ln1_g + l * Hc, ln1_b + l * Hc);
            k_mma<0><<<gQKV, 256, GEMM_SMEM>>>(p_ln, p_wqkv + (size_t)l * QKVc * Hc,
                                               nullptr, nullptr, p_qkv, Hc, QKVc);
        }

        k_init<<<512, 256>>>();
        k_favor_qk<<<NTOK / 8, 256>>>(pr_l);
        k_context<<<dim3(BHc, CTX_SPLITS), 256>>>();
        k_attn_out<<<dim3(BHc, Sc / 128), 256>>>();

        k_mma<2><<<gH, 256, GEMM_SMEM>>>(p_attn, p_wo + (size_t)l * Hc * Hc,
                                         bo_l, p_h, p_h, Hc, Hc);

        k_ln<<<NTOK / 8, 256>>>(ln2_g + l * Hc, ln2_b + l * Hc);
        k_mma<3><<<gFF, 256, GEMM_SMEM>>>(p_ln, p_w1 + (size_t)l * FFc * Hc,
                                          b1_l, nullptr, p_ff, Hc, FFc);
        k_mma<2><<<gH, 256, GEMM_SMEM>>>(p_ff, p_w2 + (size_t)l * Hc * FFc,
                                         b2_l, p_h, p_h, FFc, Hc);
    }

    k_pool<<<dim3(Bc, 64), 256>>>();
    k_fc<<<1, 512>>>(fc_w, fc_b, out);
}

// round 17
// speedup vs baseline: 1.0354x; 1.0354x over previous
#include <cuda_runtime.h>
#include <cuda_bf16.h>
#include <cstdint>
#include <math.h>

// ---------------------------------------------------------------------------
// Performer (FAVOR+) encoder. tf32 mma.sync GEMMs, 3-stage cp.async (.cg)
// pipeline, col-fastest rasterization; embed with 8-token weight reuse;
// producer-side tf32 rounding; fused FAVOR+ features; exp+ksum folded into
// context GEMM. B=8 S=8192 H=256 HEADS=8 DH=32 M=64 L=4 FF=1024
// ---------------------------------------------------------------------------

namespace {
constexpr int Bc = 8, Sc = 8192, INc = 64, Hc = 256;
constexpr int HEADSc = 8, DHc = 32, Mc = 64, Lc = 4;
constexpr int FFc = 1024;
constexpr int NTOK = Bc * Sc;          // 65536
constexpr int BHc = Bc * HEADSc;       // 64
constexpr int QKVc = 3 * Hc;           // 768
constexpr int GEMM_SMEM = 3 * (16384 + 16384);   // 96KB
constexpr int CTX_SPLITS = 32;
}

// scratch (all fp32)
__device__ float g_h[(size_t)NTOK * Hc];
__device__ float g_ln[(size_t)NTOK * Hc];
__device__ float g_qkv[(size_t)NTOK * QKVc];
__device__ float g_attn[(size_t)NTOK * Hc];
__device__ float g_ff[(size_t)NTOK * FFc];
__device__ float g_qp[(size_t)NTOK * HEADSc * Mc];   // [bh][s][m] features
__device__ float g_kp[(size_t)NTOK * HEADSc * Mc];   // [bh][s][m] RAW xp-diag
__device__ float g_ctx[BHc * Mc * DHc];
__device__ float g_ksum[BHc * Mc];
__device__ float g_bhmax[BHc];
__device__ float g_pooled[Bc * Hc];
// pre-transposed (and tf32-rounded) weights
__device__ __align__(16) float g_wqkv_t[(size_t)Lc * QKVc * Hc];
__device__ __align__(16) float g_wo_t[(size_t)Lc * Hc * Hc];
__device__ __align__(16) float g_w1_t[(size_t)Lc * FFc * Hc];
__device__ __align__(16) float g_w2_t[(size_t)Lc * Hc * FFc];

__device__ __forceinline__ void atomicMaxF(float* addr, float val) {
    if (val >= 0.0f) atomicMax((int*)addr, __float_as_int(val));
    else             atomicMin((unsigned int*)addr, __float_as_uint(val));
}

// ------------------------- helpers ----------------------------------------
__device__ __forceinline__ uint32_t smem_u32(const void* p) {
    uint32_t a;
    asm("{ .reg .u64 t; cvta.to.shared.u64 t, %1; cvt.u32.u64 %0, t; }"
        : "=r"(a) : "l"(p));
    return a;
}
__device__ __forceinline__ float rtf32(float f) {
    uint32_t r;
    asm("cvt.rna.tf32.f32 %0, %1;" : "=r"(r) : "f"(f));
    return __uint_as_float(r);
}
__device__ __forceinline__ void mma1688_tf32(float* d, const uint32_t* a,
                                             const uint32_t* b) {
    asm volatile(
        "mma.sync.aligned.m16n8k8.row.col.f32.tf32.tf32.f32 "
        "{%0,%1,%2,%3},{%4,%5,%6,%7},{%8,%9},{%0,%1,%2,%3};"
        : "+f"(d[0]), "+f"(d[1]), "+f"(d[2]), "+f"(d[3])
        : "r"(a[0]), "r"(a[1]), "r"(a[2]), "r"(a[3]), "r"(b[0]), "r"(b[1]));
}
__device__ __forceinline__ void cpasync16(uint32_t saddr, const void* g) {
    asm volatile("cp.async.cg.shared.global [%0], [%1], 16;" :: "r"(saddr), "l"(g));
}
__device__ __forceinline__ void cp_commit() {
    asm volatile("cp.async.commit_group;" ::: "memory");
}
template <int N>
__device__ __forceinline__ void cp_wait() {
    asm volatile("cp.async.wait_group %0;" :: "n"(N) : "memory");
}

// ---------------------------------------------------------------------------
// tf32 MMA GEMM: C[NTOK,Ntot] = A[NTOK,K] @ Bt[Ntot,K]^T
// CTA tile 128x128, BK=32, 3-stage cp.async pipeline, ONE sync per k-chunk.
// grid = (Ntot/128, M/128) col-fastest.
// EPI: 0=none, 2=bias+res, 3=bias+gelu(exact, rna out)
// ---------------------------------------------------------------------------
template <int EPI>
__global__ void __launch_bounds__(256, 2)
k_mma(const float* __restrict__ A, const float* __restrict__ Bt,
      const float* __restrict__ bias, const float* __restrict__ res,
      float* __restrict__ C, int K, int Ntot) {
    extern __shared__ char smem[];
    const uint32_t sbase = smem_u32(smem);
    const int t = threadIdx.x;
    const int w = t >> 5, lane = t & 31;
    const int row0 = blockIdx.y * 128, col0 = blockIdx.x * 128;
    const int wm = (w & 3) * 32, wn = (w >> 2) * 64;
    const int gid = lane >> 2, tig = lane & 3;

    float acc[2][8][4];
#pragma unroll
    for (int mi = 0; mi < 2; mi++)
#pragma unroll
        for (int ni = 0; ni < 8; ni++)
#pragma unroll
            for (int j = 0; j < 4; j++) acc[mi][ni][j] = 0.f;

    const int nsteps = K >> 5;

    auto load_step = [&](int kc, int buf) {
        const float* Ag = A + (size_t)row0 * K + kc * 32;
        const float* Bg = Bt + (size_t)col0 * K + kc * 32;
        uint32_t sA = sbase + buf * 32768u;
        uint32_t sB = sA + 16384u;
#pragma unroll
        for (int i = 0; i < 4; i++) {
            int id = t + i * 256;
            int r = id >> 3, c = id & 7;
            uint32_t so = (uint32_t)(r * 128 + ((c ^ (r & 7)) << 4));
            cpasync16(sA + so, Ag + (size_t)r * K + c * 4);
            cpasync16(sB + so, Bg + (size_t)r * K + c * 4);
        }
        cp_commit();
    };

    load_step(0, 0);
    if (nsteps > 1) load_step(1, 1);

    for (int kc = 0; kc < nsteps; kc++) {
        if (kc + 1 < nsteps) cp_wait<1>();
        else                 cp_wait<0>();
        __syncthreads();
        if (kc + 2 < nsteps) load_step(kc + 2, (kc + 2) % 3);

        const char* smA = smem + (kc % 3) * 32768;
        const char* smB = smA + 16384;
#pragma unroll
        for (int k8 = 0; k8 < 4; k8++) {
            uint32_t a[2][4];
#pragma unroll
            for (int mi = 0; mi < 2; mi++) {
#pragma unroll
                for (int j = 0; j < 4; j++) {
                    int row = wm + mi * 16 + gid + ((j & 1) ? 8 : 0);
                    int wc = k8 * 8 + tig + ((j & 2) ? 4 : 0);
                    a[mi][j] = *(const uint32_t*)(smA + row * 128 +
                                                  (((wc >> 2) ^ (row & 7)) << 4) +
                                                  (wc & 3) * 4);
                }
            }
            uint32_t b[8][2];
#pragma unroll
            for (int ni = 0; ni < 8; ni++) {
#pragma unroll
                for (int j = 0; j < 2; j++) {
                    int wc = k8 * 8 + tig + j * 4;
                    int n = wn + ni * 8 + gid;
                    b[ni][j] = *(const uint32_t*)(smB + n * 128 +
                                                  (((wc >> 2) ^ (n & 7)) << 4) +
                                                  (wc & 3) * 4);
                }
            }
#pragma unroll
            for (int mi = 0; mi < 2; mi++)
#pragma unroll
                for (int ni = 0; ni < 8; ni++) mma1688_tf32(acc[mi][ni], a[mi], b[ni]);
        }
    }

#pragma unroll
    for (int mi = 0; mi < 2; mi++) {
#pragma unroll
        for (int ni = 0; ni < 8; ni++) {
            const int rg = row0 + wm + mi * 16 + gid;
            const int cg = col0 + wn + ni * 8 + tig * 2;
            const float* ac = acc[mi][ni];
#pragma unroll
            for (int half = 0; half < 2; half++) {
                const int row = rg + half * 8;
                float v0 = ac[half * 2], v1 = ac[half * 2 + 1];
                if (EPI >= 2) { v0 += bias[cg]; v1 += bias[cg + 1]; }
                if (EPI == 3) {
                    v0 = 0.5f * v0 * (1.0f + erff(v0 * 0.70710678118654752f));
                    v1 = 0.5f * v1 * (1.0f + erff(v1 * 0.70710678118654752f));
                    v0 = rtf32(v0);
                    v1 = rtf32(v1);
                }
                const size_t base = (size_t)row * Ntot + cg;
                if (EPI == 2) { v0 += res[base]; v1 += res[base + 1]; }
                C[base] = v0;
                C[base + 1] = v1;
            }
        }
    }
}

// ---------------------------------------------------------------------------
// weight transposes (rna-rounded)
// ---------------------------------------------------------------------------
__global__ void k_wt(const float* __restrict__ W, float* __restrict__ Wt,
                     int K, int N) {
    __shared__ float tile[32][33];
    int l = blockIdx.z;
    W += (size_t)l * K * N;
    Wt += (size_t)l * K * N;
    int kb = blockIdx.x * 32, nb = blockIdx.y * 32;
    int tx = threadIdx.x, ty = threadIdx.y;
#pragma unroll
    for (int i = ty; i < 32; i += 8) tile[i][tx] = W[(size_t)(kb + i) * N + nb + tx];
    __syncthreads();
#pragma unroll
    for (int i = ty; i < 32; i += 8)
        Wt[(size_t)(nb + i) * K + kb + tx] = rtf32(tile[tx][i]);
}

__global__ void k_wt_qkv(const float* __restrict__ wq, const float* __restrict__ wk,
                         const float* __restrict__ wv, float* __restrict__ Wt) {
    __shared__ float tile[32][33];
    int l = blockIdx.z;
    int kb = blockIdx.x * 32, nb = blockIdx.y * 32;
    const float* W = (nb < 256) ? wq : (nb < 512 ? wk : wv);
    int nloc = nb & 255;
    W += (size_t)l * Hc * Hc;
    Wt += (size_t)l * QKVc * Hc;
    int tx = threadIdx.x, ty = threadIdx.y;
#pragma unroll
    for (int i = ty; i < 32; i += 8)
        tile[i][tx] = W[(size_t)(kb + i) * Hc + nloc + tx];
    __syncthreads();
#pragma unroll
    for (int i = ty; i < 32; i += 8)
        Wt[(size_t)(nb + i) * Hc + kb + tx] = rtf32(tile[tx][i]);
}

// ---------------------------------------------------------------------------
// embed: 8 tokens/block; thread = out column; w loaded once per block and
// reused across 8 tokens in registers. grid NTOK/8, block 256.
// ---------------------------------------------------------------------------
__global__ void k_embed(const float* __restrict__ x, const float* __restrict__ w,
                        const float* __restrict__ b, const float* __restrict__ pos) {
    __shared__ float xs[8][INc];
    int t = threadIdx.x;
    size_t n0 = (size_t)blockIdx.x * 8;
    for (int i = t; i < 8 * INc; i += 256)
        xs[i >> 6][i & 63] = x[n0 * INc + i];
    __syncthreads();
    int s0 = (int)(n0 & (Sc - 1));
    float bias = b[t];
    float acc[8];
#pragma unroll
    for (int j = 0; j < 8; j++) acc[j] = bias + pos[(size_t)(s0 + j) * Hc + t];
#pragma unroll 8
    for (int d = 0; d < INc; d++) {
        float wv = w[(size_t)d * Hc + t];
#pragma unroll
        for (int j = 0; j < 8; j++) acc[j] += xs[j][d] * wv;
    }
#pragma unroll
    for (int j = 0; j < 8; j++) g_h[(n0 + j) * Hc + t] = acc[j];
}

// ---------------------------------------------------------------------------
// layernorm, warp per token, float4, rna out
// ---------------------------------------------------------------------------
__global__ void k_ln(const float* __restrict__ gamma, const float* __restrict__ beta) {
    int w = threadIdx.x >> 5, lane = threadIdx.x & 31;
    size_t n = (size_t)blockIdx.x * 8 + w;
    const float4* row = (const float4*)(g_h + n * Hc);
    float4 a = row[lane * 2], c = row[lane * 2 + 1];
    float s = a.x + a.y + a.z + a.w + c.x + c.y + c.z + c.w;
#pragma unroll
    for (int o = 16; o; o >>= 1) s += __shfl_xor_sync(~0u, s, o);
    float mu = s * (1.0f / Hc);
    float dx[8] = {a.x - mu, a.y - mu, a.z - mu, a.w - mu,
                   c.x - mu, c.y - mu, c.z - mu, c.w - mu};
    float v = 0.f;
#pragma unroll
    for (int i = 0; i < 8; i++) v += dx[i] * dx[i];
#pragma unroll
    for (int o = 16; o; o >>= 1) v += __shfl_xor_sync(~0u, v, o);
    float rstd = rsqrtf(v * (1.0f / Hc) + 1e-5f);
    float4 g0 = *(const float4*)(gamma + lane * 8);
    float4 g1 = *(const float4*)(gamma + lane * 8 + 4);
    float4 b0 = *(const float4*)(beta + lane * 8);
    float4 b1 = *(const float4*)(beta + lane * 8 + 4);
    float4 o0, o1;
    o0.x = rtf32(dx[0] * rstd * g0.x + b0.x);
    o0.y = rtf32(dx[1] * rstd * g0.y + b0.y);
    o0.z = rtf32(dx[2] * rstd * g0.z + b0.z);
    o0.w = rtf32(dx[3] * rstd * g0.w + b0.w);
    o1.x = rtf32(dx[4] * rstd * g1.x + b1.x);
    o1.y = rtf32(dx[5] * rstd * g1.y + b1.y);
    o1.z = rtf32(dx[6] * rstd * g1.z + b1.z);
    o1.w = rtf32(dx[7] * rstd * g1.w + b1.w);
    float4* orow = (float4*)(g_ln + n * Hc);
    orow[lane * 2] = o0;
    orow[lane * 2 + 1] = o1;
}

// ---------------------------------------------------------------------------
__global__ void k_init() {
    int i = blockIdx.x * blockDim.x + threadIdx.x;
    if (i < BHc * Mc * DHc) g_ctx[i] = 0.f;
    if (i < BHc * Mc) g_ksum[i] = 0.f;
    if (i < BHc) g_bhmax[i] = -INFINITY;
    if (i < Bc * Hc) g_pooled[i] = 0.f;
}

// ---------------------------------------------------------------------------
// FAVOR+ q and k feature maps in ONE launch. block=256 (8 warps),
// grid = NTOK/8. warp w handles head w for 8 consecutive tokens.
// ---------------------------------------------------------------------------
__global__ void k_favor_qk(const float* __restrict__ proj) {
    __shared__ float ps[Mc * 33];
    int t = threadIdx.x;
    for (int i = t; i < Mc * DHc; i += 256) ps[(i >> 5) * 33 + (i & 31)] = proj[i];
    __syncthreads();
    int w = t >> 5, lane = t & 31;
    int n0 = blockIdx.x * 8;
    int b = n0 / Sc;
    int bh = b * HEADSc + w;
    const float NORM = 0.4204482076268573f;  // 32^-0.25

    // ---------------- q features ----------------
#pragma unroll
    for (int it = 0; it < 2; it++) {
        float qv[4], diag[4];
#pragma unroll
        for (int j = 0; j < 4; j++) {
            qv[j] = g_qkv[(size_t)(n0 + it * 4 + j) * QKVc + w * DHc + lane] * NORM;
            float sq = qv[j] * qv[j];
#pragma unroll
            for (int o = 16; o; o >>= 1) sq += __shfl_xor_sync(~0u, sq, o);
            diag[j] = 0.5f * sq;
        }
        float xp0[4] = {0.f, 0.f, 0.f, 0.f}, xp1[4] = {0.f, 0.f, 0.f, 0.f};
#pragma unroll
        for (int d = 0; d < DHc; d++) {
            float p0 = ps[lane * 33 + d];
            float p1 = ps[(lane + 32) * 33 + d];
#pragma unroll
            for (int j = 0; j < 4; j++) {
                float qd = __shfl_sync(~0u, qv[j], d);
                xp0[j] += qd * p0;
                xp1[j] += qd * p1;
            }
        }
#pragma unroll
        for (int j = 0; j < 4; j++) {
            float mx = fmaxf(xp0[j], xp1[j]);
#pragma unroll
            for (int o = 16; o; o >>= 1) mx = fmaxf(mx, __shfl_xor_sync(~0u, mx, o));
            int n = n0 + it * 4 + j;
            size_t idx = ((size_t)bh * Sc + (n & (Sc - 1))) * Mc + lane;
            g_qp[idx]      = 0.125f * (__expf(xp0[j] - diag[j] - mx) + 1e-4f);
            g_qp[idx + 32] = 0.125f * (__expf(xp1[j] - diag[j] - mx) + 1e-4f);
        }
    }

    // ---------------- k raw features + per-bh max ----------------
    float wmax = -INFINITY;
#pragma unroll
    for (int it = 0; it < 2; it++) {
        float kv[4], diag[4];
#pragma unroll
        for (int j = 0; j < 4; j++) {
            kv[j] = g_qkv[(size_t)(n0 + it * 4 + j) * QKVc + Hc + w * DHc + lane] * NORM;
            float sq = kv[j] * kv[j];
#pragma unroll
            for (int o = 16; o; o >>= 1) sq += __shfl_xor_sync(~0u, sq, o);
            diag[j] = 0.5f * sq;
        }
        float xp0[4] = {0.f, 0.f, 0.f, 0.f}, xp1[4] = {0.f, 0.f, 0.f, 0.f};
#pragma unroll
        for (int d = 0; d < DHc; d++) {
            float p0 = ps[lane * 33 + d];
            float p1 = ps[(lane + 32) * 33 + d];
#pragma unroll
            for (int j = 0; j < 4; j++) {
                float kd = __shfl_sync(~0u, kv[j], d);
                xp0[j] += kd * p0;
                xp1[j] += kd * p1;
            }
        }
#pragma unroll
        for (int j = 0; j < 4; j++) {
            wmax = fmaxf(wmax, fmaxf(xp0[j], xp1[j]));
            int n = n0 + it * 4 + j;
            size_t idx = ((size_t)bh * Sc + (n & (Sc - 1))) * Mc + lane;
            g_kp[idx]      = xp0[j] - diag[j];
            g_kp[idx + 32] = xp1[j] - diag[j];
        }
    }
#pragma unroll
    for (int o = 16; o; o >>= 1) wmax = fmaxf(wmax, __shfl_xor_sync(~0u, wmax, o));
    if (lane == 0) atomicMaxF(&g_bhmax[bh], wmax);
}

// ---------------------------------------------------------------------------
// context[m,e] = sum_n kp'[n,m] * v[n,e], kp' = 0.125*(exp(raw-mx)+1e-4)
// applied on tile load; ksum accumulated as by-product. split-K over n.
// grid (BHc, CTX_SPLITS), block 256.
// ---------------------------------------------------------------------------
__global__ void k_context() {
    int bh = blockIdx.x, split = blockIdx.y;
    int b = bh >> 3, h = bh & 7;
    const float mx = g_bhmax[bh];
    int t = threadIdx.x;
    int m = t & 63, eb = (t >> 6) * 8;
    __shared__ float kps[16][64];
    __shared__ __align__(16) float vs[16][32];
    float acc[8];
#pragma unroll
    for (int j = 0; j < 8; j++) acc[j] = 0.f;
    float ksl = 0.f;
    int nbase = split * (Sc / CTX_SPLITS);
    for (int tile = 0; tile < (Sc / CTX_SPLITS) / 16; tile++) {
        int n0 = nbase + tile * 16;
        for (int i = t; i < 16 * 64; i += 256) {
            int r = i >> 6, mm = i & 63;
            float raw = g_kp[((size_t)bh * Sc + n0 + r) * Mc + mm];
            kps[r][mm] = 0.125f * (__expf(raw - mx) + 1e-4f);
        }
        for (int i = t; i < 16 * 32; i += 256) {
            int r = i >> 5, e = i & 31;
            vs[r][e] = g_qkv[((size_t)(b * Sc + n0 + r)) * QKVc + 2 * Hc + h * DHc + e];
        }
        __syncthreads();
#pragma unroll
        for (int r = 0; r < 16; r++) {
            float kvv = kps[r][m];
            ksl += kvv;
            float4 va = *(const float4*)&vs[r][eb];
            float4 vb = *(const float4*)&vs[r][eb + 4];
            acc[0] += kvv * va.x; acc[1] += kvv * va.y;
            acc[2] += kvv * va.z; acc[3] += kvv * va.w;
            acc[4] += kvv * vb.x; acc[5] += kvv * vb.y;
            acc[6] += kvv * vb.z; acc[7] += kvv * vb.w;
        }
        __syncthreads();
    }
#pragma unroll
    for (int j = 0; j < 8; j++)
        atomicAdd(&g_ctx[(bh * Mc + m) * DHc + eb + j], acc[j]);
    if (t < 64) atomicAdd(&g_ksum[bh * Mc + m], ksl);
}

// ---------------------------------------------------------------------------
// attn out: out[n, h*32+e] = (qp[n,:] @ ctx) / (qp[n,:] . ksum), rna out
// ---------------------------------------------------------------------------
__global__ void __launch_bounds__(256) k_attn_out() {
    int bh = blockIdx.x;
    int b = bh >> 3, h = bh & 7;
    int n0 = blockIdx.y * 128;
    int t = threadIdx.x;
    __shared__ float qps[128 * 68];
    __shared__ __align__(16) float ctxs[64 * 36];
    __shared__ float ks[64];
    const float4* qpg = (const float4*)(g_qp + ((size_t)bh * Sc + n0) * Mc);
    for (int i = t; i < 2048; i += 256) {
        int r = i >> 4, c = i & 15;
        float4 v = qpg[r * 16 + c];
        float* dst = &qps[r * 68 + c * 4];
        dst[0] = v.x; dst[1] = v.y; dst[2] = v.z; dst[3] = v.w;
    }
    for (int i = t; i < 64 * 32; i += 256) {
        int m = i >> 5, e = i & 31;
        ctxs[m * 36 + e] = g_ctx[(bh * Mc + m) * DHc + e];
    }
    if (t < 64) ks[t] = g_ksum[bh * Mc + t];
    __syncthreads();

    int tok = t >> 1, eg = (t & 1) * 16;
    float acc[16];
#pragma unroll
    for (int i = 0; i < 16; i++) acc[i] = 0.f;
    float dp = 0.f;
#pragma unroll 8
    for (int m = 0; m < 64; m++) {
        float qv = qps[tok * 68 + m];
        dp += qv * ks[m];
        const float4* c4 = (const float4*)&ctxs[m * 36 + eg];
        float4 c0 = c4[0], c1 = c4[1], c2 = c4[2], c3 = c4[3];
        acc[0] += qv * c0.x; acc[1] += qv * c0.y; acc[2] += qv * c0.z; acc[3] += qv * c0.w;
        acc[4] += qv * c1.x; acc[5] += qv * c1.y; acc[6] += qv * c1.z; acc[7] += qv * c1.w;
        acc[8] += qv * c2.x; acc[9] += qv * c2.y; acc[10] += qv * c2.z; acc[11] += qv * c2.w;
        acc[12] += qv * c3.x; acc[13] += qv * c3.y; acc[14] += qv * c3.z; acc[15] += qv * c3.w;
    }
    float inv = 1.0f / dp;
    float* outp = g_attn + ((size_t)(b * Sc + n0 + tok)) * Hc + h * DHc + eg;
#pragma unroll
    for (int q = 0; q < 4; q++) {
        float4 o;
        o.x = rtf32(acc[q * 4 + 0] * inv);
        o.y = rtf32(acc[q * 4 + 1] * inv);
        o.z = rtf32(acc[q * 4 + 2] * inv);
        o.w = rtf32(acc[q * 4 + 3] * inv);
        *(float4*)(outp + q * 4) = o;
    }
}

__global__ void k_pool() {
    int b = blockIdx.x, chunk = blockIdx.y, t = threadIdx.x;
    float s = 0.f;
    int r0 = chunk * 128;
#pragma unroll 4
    for (int r = 0; r < 128; r++) s += g_h[(size_t)(b * Sc + r0 + r) * Hc + t];
    atomicAdd(&g_pooled[b * Hc + t], s);
}

__global__ void k_fc(const float* __restrict__ fc_w, const float* __restrict__ fc_b,
                     float* __restrict__ out) {
    int t = threadIdx.x, w = t >> 5, lane = t & 31;
    if (w >= 16) return;
    int b = w >> 1, c = w & 1;
    float s = 0.f;
#pragma unroll
    for (int k = lane; k < Hc; k += 32) s += g_pooled[b * Hc + k] * fc_w[k * 2 + c];
#pragma unroll
    for (int o = 16; o; o >>= 1) s += __shfl_xor_sync(~0u, s, o);
    if (lane == 0) out[b * 2 + c] = s * (1.0f / Sc) + fc_b[c];
}

// ---------------------------------------------------------------------------
// launch  (k_mma<0> kept at launch index 3 for profiling)
// ---------------------------------------------------------------------------
extern "C" void kernel_launch(void* const* d_in, const int* /*in_sizes*/, int /*n_in*/,
                              void* d_out, int /*out_size*/) {
    const float* x     = (const float*)d_in[0];
    const float* emb_w = (const float*)d_in[1];
    const float* emb_b = (const float*)d_in[2];
    const float* pos   = (const float*)d_in[3];
    const float* ln1_g = (const float*)d_in[4];
    const float* ln1_b = (const float*)d_in[5];
    const float* wq    = (const float*)d_in[6];
    const float* wk    = (const float*)d_in[7];
    const float* wv    = (const float*)d_in[8];
    const float* wo    = (const float*)d_in[9];
    const float* bo    = (const float*)d_in[10];
    const float* ln2_g = (const float*)d_in[11];
    const float* ln2_b = (const float*)d_in[12];
    const float* w1    = (const float*)d_in[13];
    const float* b1    = (const float*)d_in[14];
    const float* w2    = (const float*)d_in[15];
    const float* b2    = (const float*)d_in[16];
    const float* proj  = (const float*)d_in[17];
    const float* fc_w  = (const float*)d_in[18];
    const float* fc_b  = (const float*)d_in[19];
    float* out = (float*)d_out;

    static float *p_h = nullptr, *p_ln = nullptr, *p_qkv = nullptr, *p_attn = nullptr,
                 *p_ff = nullptr, *p_wqkv = nullptr, *p_wo = nullptr,
                 *p_w1 = nullptr, *p_w2 = nullptr;
    if (!p_h) {
        cudaGetSymbolAddress((void**)&p_h, g_h);
        cudaGetSymbolAddress((void**)&p_ln, g_ln);
        cudaGetSymbolAddress((void**)&p_qkv, g_qkv);
        cudaGetSymbolAddress((void**)&p_attn, g_attn);
        cudaGetSymbolAddress((void**)&p_ff, g_ff);
        cudaGetSymbolAddress((void**)&p_wqkv, g_wqkv_t);
        cudaGetSymbolAddress((void**)&p_wo, g_wo_t);
        cudaGetSymbolAddress((void**)&p_w1, g_w1_t);
        cudaGetSymbolAddress((void**)&p_w2, g_w2_t);
        cudaFuncSetAttribute(k_mma<0>, cudaFuncAttributeMaxDynamicSharedMemorySize,
                             GEMM_SMEM);
        cudaFuncSetAttribute(k_mma<2>, cudaFuncAttributeMaxDynamicSharedMemorySize,
                             GEMM_SMEM);
        cudaFuncSetAttribute(k_mma<3>, cudaFuncAttributeMaxDynamicSharedMemorySize,
                             GEMM_SMEM);
    }

    dim3 wtb(32, 8);
    dim3 gQKV(QKVc / 128, NTOK / 128);   // (6, 512) col-fastest
    dim3 gH(Hc / 128, NTOK / 128);       // (2, 512)
    dim3 gFF(FFc / 128, NTOK / 128);     // (8, 512)

    // launch 0..3: embed, ln1(l0), wt_qkv, mma_qkv(l0)  -> k_mma<0> @ index 3
    k_embed<<<NTOK / 8, 256>>>(x, emb_w, emb_b, pos);
    k_ln<<<NTOK / 8, 256>>>(ln1_g, ln1_b);
    k_wt_qkv<<<dim3(Hc / 32, QKVc / 32, Lc), wtb>>>(wq, wk, wv, p_wqkv);
    k_mma<0><<<gQKV, 256, GEMM_SMEM>>>(p_ln, p_wqkv, nullptr, nullptr, p_qkv,
                                       Hc, QKVc);
    k_wt<<<dim3(Hc / 32, Hc / 32, Lc), wtb>>>(wo, p_wo, Hc, Hc);
    k_wt<<<dim3(Hc / 32, FFc / 32, Lc), wtb>>>(w1, p_w1, Hc, FFc);
    k_wt<<<dim3(FFc / 32, Hc / 32, Lc), wtb>>>(w2, p_w2, FFc, Hc);

    for (int l = 0; l < Lc; l++) {
        const float* bo_l = bo + (size_t)l * Hc;
        const float* b1_l = b1 + (size_t)l * FFc;
        const float* b2_l = b2 + (size_t)l * Hc;
        const float* pr_l = proj + (size_t)l * Mc * DHc;

        if (l > 0) {
            k_ln<<<NTOK / 8, 256>>>(ln1_g + l * Hc, ln1_b + l * Hc);
            k_mma<0><<<gQKV, 256, GEMM_SMEM>>>(p_ln, p_wqkv + (size_t)l * QKVc * Hc,
                                               nullptr, nullptr, p_qkv, Hc, QKVc);
        }

        k_init<<<512, 256>>>();
        k_favor_qk<<<NTOK / 8, 256>>>(pr_l);
        k_context<<<dim3(BHc, CTX_SPLITS), 256>>>();
        k_attn_out<<<dim3(BHc, Sc / 128), 256>>>();

        k_mma<2><<<gH, 256, GEMM_SMEM>>>(p_attn, p_wo + (size_t)l * Hc * Hc,
                                         bo_l, p_h, p_h, Hc, Hc);

        k_ln<<<NTOK / 8, 256>>>(ln2_g + l * Hc, ln2_b + l * Hc);
        k_mma<3><<<gFF, 256, GEMM_SMEM>>>(p_ln, p_w1 + (size_t)l * FFc * Hc,
                                          b1_l, nullptr, p_ff, Hc, FFc);
        k_mma<2><<<gH, 256, GEMM_SMEM>>>(p_ff, p_w2 + (size_t)l * Hc * FFc,
                                         b2_l, p_h, p_h, FFc, Hc);
    }

    k_pool<<<dim3(Bc, 64), 256>>>();
    k_fc<<<1, 512>>>(fc_w, fc_b, out);
}